// round 3
// baseline (speedup 1.0000x reference)
#include <cuda_runtime.h>
#include <math.h>

#define NS   65536
#define DD   256
#define KK   10
#define NCH  10          // sample chunks per (class,tile)
#define SORT_T 4096      // 16 blocks x 256 sorting threads
#define SPT  16          // samples per sorting thread
#define NTILE 3          // (0,0),(0,1),(1,1) 128x128 tiles of 256x256
#define TRI_N 32896      // 256*257/2

typedef unsigned long long ull;

// ----------------- device scratch (static globals; no allocation) -----------------
__device__ int    g_is64;
__device__ int    g_hist[KK * SORT_T];
__device__ int    g_count[KK];
__device__ int    g_off[KK];
__device__ int    g_perm[NS];
__device__ float  g_part[NCH * KK * NTILE][16384];   // ~19.7 MB partial tiles
__device__ float  g_cov[KK][DD * DD];
__device__ float  g_gram[DD * DD];
__device__ double g_logdet[KK + 1];                  // [0]=gram, [1..10]=classes

// ----------------- f32x2 helpers (sm_103a packed fp32 FMA) -----------------
__device__ __forceinline__ ull pk2(float x, float y) {
    ull d;
    asm("mov.b64 %0, {%1, %2};" : "=l"(d)
        : "r"(__float_as_uint(x)), "r"(__float_as_uint(y)));
    return d;
}
__device__ __forceinline__ ull ffma2(ull a, ull b, ull c) {
    ull d;
    asm("fma.rn.f32x2 %0, %1, %2, %3;" : "=l"(d) : "l"(a), "l"(b), "l"(c));
    return d;
}
__device__ __forceinline__ float2 upk2(ull d) {
    unsigned int lo, hi;
    asm("mov.b64 {%0, %1}, %2;" : "=r"(lo), "=r"(hi) : "l"(d));
    return make_float2(__uint_as_float(lo), __uint_as_float(hi));
}

__device__ __forceinline__ int tri(int i) { return (i * (i + 1)) >> 1; }

// ----------------- 0. label dtype detection (int64 vs int32) -----------------
__global__ void k_detect(const int* __restrict__ Y) {
    __shared__ int bad;
    if (threadIdx.x == 0) bad = 0;
    __syncthreads();
    int viol = 0;
    // First 2048 32-bit words. If Y is little-endian int64 with labels in
    // [0,10), every odd word is 0. If int32, P(1024 odd labels all 0) ~ 0.
    for (int w = 0; w < 8; ++w) {
        int idx = threadIdx.x * 8 + w;
        int v = Y[idx];
        if (idx & 1) { if (v != 0) viol = 1; }
        else         { if (v < 0 || v >= KK) viol = 1; }
    }
    if (viol) atomicOr(&bad, 1);
    __syncthreads();
    if (threadIdx.x == 0) g_is64 = bad ? 0 : 1;
}

// ----------------- 1-4. deterministic stable counting sort of labels -----------------
__global__ void k_hist(const int* __restrict__ Y) {
    int t = blockIdx.x * blockDim.x + threadIdx.x;   // 0..4095
    int cnt[KK];
#pragma unroll
    for (int c = 0; c < KK; ++c) cnt[c] = 0;
    int is64 = g_is64;
    int base = t * SPT;
    for (int q = 0; q < SPT; ++q) {
        int i = base + q;
        int lab = is64 ? Y[2 * i] : Y[i];
        cnt[lab]++;
    }
#pragma unroll
    for (int c = 0; c < KK; ++c) g_hist[c * SORT_T + t] = cnt[c];
}

__global__ void k_scan() {   // one block per class: exclusive scan of 4096 counts
    int c = blockIdx.x, tid = threadIdx.x;
    int* h = g_hist + c * SORT_T;
    int loc[16];
    int base = tid * 16;
    int tsum = 0;
#pragma unroll
    for (int q = 0; q < 16; ++q) { loc[q] = h[base + q]; tsum += loc[q]; }
    __shared__ int sh[256];
    sh[tid] = tsum;
    __syncthreads();
    for (int st = 1; st < 256; st <<= 1) {
        int v = 0;
        if (tid >= st) v = sh[tid - st];
        __syncthreads();
        if (tid >= st) sh[tid] += v;
        __syncthreads();
    }
    int run = sh[tid] - tsum;   // exclusive prefix for this thread's first entry
#pragma unroll
    for (int q = 0; q < 16; ++q) { h[base + q] = run; run += loc[q]; }
    if (tid == 255) g_count[c] = sh[255];
}

__global__ void k_offs() {
    if (threadIdx.x == 0 && blockIdx.x == 0) {
        int a = 0;
        for (int c = 0; c < KK; ++c) { g_off[c] = a; a += g_count[c]; }
    }
}

__global__ void k_scat(const int* __restrict__ Y) {
    int t = blockIdx.x * blockDim.x + threadIdx.x;
    int cnt[KK];
#pragma unroll
    for (int c = 0; c < KK; ++c) cnt[c] = 0;
    int is64 = g_is64;
    int base = t * SPT;
    for (int q = 0; q < SPT; ++q) {
        int i = base + q;
        int lab = is64 ? Y[2 * i] : Y[i];
        int pos = g_off[lab] + g_hist[lab * SORT_T + t] + cnt[lab];
        cnt[lab]++;
        g_perm[pos] = i;
    }
}

// ----------------- 5. grouped SYRK via packed f32x2 FMA -----------------
// block b: ch = b/30, rem = b%30, k = rem/3, tile t = rem%3
// tile t: 0 -> (bi,bj)=(0,0), 1 -> (0,1), 2 -> (1,1)   [128x128 feature tiles]
__global__ void __launch_bounds__(256, 2) k_syrk(const float* __restrict__ X) {
    int b = blockIdx.x;
    int ch = b / (KK * NTILE);
    int rem = b % (KK * NTILE);
    int k = rem / NTILE;
    int t = rem % NTILE;
    int bi = (t == 2) ? 1 : 0;
    int bj = (t == 0) ? 0 : 1;
    bool diag = (bi == bj);

    int off = g_off[k], cnt = g_count[k];
    int len = (cnt + NCH - 1) / NCH;
    int sb = off + ch * len;
    int se = off + cnt;
    if (sb + len < se) se = sb + len;

    __shared__ __align__(16) float As[16][128];
    __shared__ __align__(16) float Bs[16][128];
    __shared__ int sperm[16];

    int tid = threadIdx.x;
    int tx = tid & 15, ty = tid >> 4;

    ull acc[8][4];
#pragma unroll
    for (int i = 0; i < 8; ++i)
#pragma unroll
        for (int j = 0; j < 4; ++j) acc[i][j] = 0ULL;

    float (*Bp)[128] = diag ? As : Bs;

    for (int s0 = sb; s0 < se; s0 += 16) {
        __syncthreads();
        if (tid < 16) sperm[tid] = (s0 + tid < se) ? g_perm[s0 + tid] : -1;
        __syncthreads();
        {
            int row = ty;
            int col = tx * 8;
            int sp = sperm[row];
            float4 z = make_float4(0.f, 0.f, 0.f, 0.f);
            float4 v0 = z, v1 = z, w0 = z, w1 = z;
            if (sp >= 0) {
                const float4* xr = (const float4*)(X + (size_t)sp * DD);
                v0 = xr[(bi * 128 + col) >> 2];
                v1 = xr[((bi * 128 + col) >> 2) + 1];
                if (!diag) {
                    w0 = xr[(bj * 128 + col) >> 2];
                    w1 = xr[((bj * 128 + col) >> 2) + 1];
                }
            }
            *(float4*)&As[row][col] = v0;
            *(float4*)&As[row][col + 4] = v1;
            if (!diag) {
                *(float4*)&Bs[row][col] = w0;
                *(float4*)&Bs[row][col + 4] = w1;
            }
        }
        __syncthreads();

#pragma unroll
        for (int q = 0; q < 16; ++q) {
            float a[8];
            *(float4*)(a)     = *(const float4*)&As[q][ty * 8];
            *(float4*)(a + 4) = *(const float4*)&As[q][ty * 8 + 4];
            ulonglong2 b0 = *(const ulonglong2*)&Bp[q][tx * 8];
            ulonglong2 b1 = *(const ulonglong2*)&Bp[q][tx * 8 + 4];
            ull bp[4];
            bp[0] = b0.x; bp[1] = b0.y; bp[2] = b1.x; bp[3] = b1.y;
            ull ap[8];
#pragma unroll
            for (int i = 0; i < 8; ++i) ap[i] = pk2(a[i], a[i]);
#pragma unroll
            for (int i = 0; i < 8; ++i)
#pragma unroll
                for (int j = 0; j < 4; ++j)
                    acc[i][j] = ffma2(ap[i], bp[j], acc[i][j]);
        }
    }

    float* outp = g_part[b];
#pragma unroll
    for (int i = 0; i < 8; ++i)
#pragma unroll
        for (int j2 = 0; j2 < 4; ++j2) {
            float2 v = upk2(acc[i][j2]);
            int row = ty * 8 + i, col = tx * 8 + j2 * 2;
            *(float2*)&outp[row * 128 + col] = v;
        }
}

// ----------------- 6. reduce chunk partials -> full mirrored cov -----------------
__global__ void k_reduce() {
    int r = blockIdx.x;           // k*3 + t
    int k = r / NTILE, t = r % NTILE;
    int tid = threadIdx.x;
    for (int e = tid; e < 16384; e += 256) {
        float sum = 0.f;
#pragma unroll
        for (int ch = 0; ch < NCH; ++ch) sum += g_part[ch * (KK * NTILE) + r][e];
        int i = e >> 7, j = e & 127;
        if (t == 0)      g_cov[k][i * DD + j] = sum;
        else if (t == 2) g_cov[k][(128 + i) * DD + 128 + j] = sum;
        else {
            g_cov[k][i * DD + 128 + j] = sum;
            g_cov[k][(128 + j) * DD + i] = sum;
        }
    }
}

__global__ void k_gram() {
    int e = blockIdx.x * 256 + threadIdx.x;
    float s = 0.f;
#pragma unroll
    for (int k = 0; k < KK; ++k) s += g_cov[k][e];
    g_gram[e] = s;
}

// ----------------- 7. blocked Cholesky (packed lower tri in smem) + logdet -----------------
__global__ void k_chol() {
    extern __shared__ float Ls[];    // TRI_N floats = 131584 bytes
    __shared__ float sinv;
    __shared__ double red[256];

    int b = blockIdx.x;
    const float* A = (b == 0) ? g_gram : g_cov[b - 1];
    float s;
    if (b == 0) s = 256.0f / (65536.0f * 0.01f);
    else {
        double tr = (double)g_count[b - 1] + 1e-8;
        s = (float)(256.0 / (tr * 0.01));
    }
    int tid = threadIdx.x;

    // load I + s*A, packed lower triangle
    for (int p = tid; p < TRI_N; p += 256) {
        int i = (int)((sqrtf(8.f * (float)p + 1.f) - 1.f) * 0.5f);
        while (tri(i + 1) <= p) ++i;
        while (tri(i) > p) --i;
        int j = p - tri(i);
        Ls[p] = ((i == j) ? 1.f : 0.f) + s * A[i * DD + j];
    }
    __syncthreads();

    for (int j0 = 0; j0 < DD; j0 += 16) {
        // unblocked full-height panel factor, cols j0..j0+15
        for (int jj = 0; jj < 16; ++jj) {
            int j = j0 + jj;
            if (tid == 0) {
                float d = Ls[tri(j) + j];
                float rr = sqrtf(d);
                Ls[tri(j) + j] = rr;
                sinv = 1.f / rr;
            }
            __syncthreads();
            float iv = sinv;
            for (int i = j + 1 + tid; i < DD; i += 256) Ls[tri(i) + j] *= iv;
            __syncthreads();
            int cend = j0 + 16;
            for (int i = j + 1 + tid; i < DD; i += 256) {
                float lij = Ls[tri(i) + j];
                int cm = (i < cend - 1) ? i : cend - 1;
                for (int c = j + 1; c <= cm; ++c)
                    Ls[tri(i) + c] -= lij * Ls[tri(c) + j];
            }
            __syncthreads();
        }
        // rank-16 trailing update: each thread owns one trailing column
        int c = j0 + 16 + tid;
        if (c < DD) {
            float lc[16];
#pragma unroll
            for (int q = 0; q < 16; ++q) lc[q] = Ls[tri(c) + j0 + q];
            int cd = c - j0;
            for (int rrow = c; rrow < DD; ++rrow) {
                int base = tri(rrow) + j0;
                float acc = Ls[base + cd];
#pragma unroll
                for (int q = 0; q < 16; ++q) acc -= Ls[base + q] * lc[q];
                Ls[base + cd] = acc;
            }
        }
        __syncthreads();
    }

    // logdet = 2 * sum(ln L_ii), fp64 tree reduce (deterministic)
    red[tid] = log((double)Ls[tri(tid) + tid]);
    __syncthreads();
    for (int st = 128; st > 0; st >>= 1) {
        if (tid < st) red[tid] += red[tid + st];
        __syncthreads();
    }
    if (tid == 0) g_logdet[b] = 2.0 * red[0];
}

// ----------------- 8. finalize -----------------
__global__ void k_final(float* out) {
    double disc = 0.5 * g_logdet[0];
    double comp = 0.0;
    for (int k = 0; k < KK; ++k) {
        double tr = (double)g_count[k] + 1e-8;
        comp += g_logdet[k + 1] * tr;
    }
    comp = comp / 65536.0 / 2.0;
    out[0] = (float)(-disc + comp);   // GAM2 * (-discrimn) + compress
    out[1] = (float)disc;
    out[2] = (float)comp;
    out[3] = (float)disc;
    out[4] = (float)comp;
}

// ----------------- host -----------------
extern "C" void kernel_launch(void* const* d_in, const int* in_sizes, int n_in,
                              void* d_out, int out_size) {
    // identify inputs by size: X has NS*DD elements, Y has NS
    const float* X = 0;
    const int* Y = 0;
    for (int i = 0; i < n_in; ++i) {
        if (in_sizes[i] == NS * DD) X = (const float*)d_in[i];
        else if (in_sizes[i] == NS) Y = (const int*)d_in[i];
    }
    if (!X) X = (const float*)d_in[0];
    if (!Y) Y = (const int*)d_in[1];
    float* out = (float*)d_out;

    k_detect<<<1, 256>>>(Y);
    k_hist<<<16, 256>>>(Y);
    k_scan<<<KK, 256>>>();
    k_offs<<<1, 32>>>();
    k_scat<<<16, 256>>>(Y);
    k_syrk<<<NCH * KK * NTILE, 256>>>(X);
    k_reduce<<<KK * NTILE, 256>>>();
    k_gram<<<256, 256>>>();
    cudaFuncSetAttribute(k_chol, cudaFuncAttributeMaxDynamicSharedMemorySize,
                         TRI_N * (int)sizeof(float));
    k_chol<<<KK + 1, 256, TRI_N * sizeof(float)>>>();
    k_final<<<1, 1>>>(out);
    (void)out_size;
}